// round 2
// baseline (speedup 1.0000x reference)
#include <cuda_runtime.h>
#include <math.h>

// Problem constants
#define BROWS 16384
#define QDIM  1024

// ---------------------------------------------------------------------------
// Scratch (static device globals; allocation at module load, allowed)
// ---------------------------------------------------------------------------
__device__ float g_h1   [BROWS * 4 * QDIM];  // 268 MB
__device__ float g_h2   [BROWS * 2 * QDIM];  // 134 MB
__device__ float g_p    [BROWS * 2 * QDIM];  // 134 MB
__device__ float g_amp  [BROWS * QDIM];      //  67 MB
__device__ float g_phase[BROWS * QDIM];      //  67 MB
__device__ float g_qs   [BROWS * QDIM];      //  67 MB
__device__ float g_v    [BROWS * QDIM];      //  67 MB

// ---------------------------------------------------------------------------
// First layer: y = x @ W^T + b (K=2), LN, activation.  One block per row.
// ACT: 0 = exact gelu, 1 = silu
// ---------------------------------------------------------------------------
template<int N, int ACT>
__global__ __launch_bounds__(256)
void first_layer_kernel(const float* __restrict__ x,
                        const float* __restrict__ W,   // (N,2) row-major
                        const float* __restrict__ b,
                        const float* __restrict__ g,
                        const float* __restrict__ be,
                        float* __restrict__ out) {
    constexpr int T = 256;
    constexpr int PER = N / T;
    const int row = blockIdx.x;
    const int t = threadIdx.x;
    const float x0 = x[row * 2 + 0];
    const float x1 = x[row * 2 + 1];

    float yv[PER];
    float s = 0.f, ss = 0.f;
#pragma unroll
    for (int i = 0; i < PER; i++) {
        const int j = t + i * T;
        const float y = fmaf(x0, W[2 * j], fmaf(x1, W[2 * j + 1], b[j]));
        yv[i] = y;
        s += y;
        ss += y * y;
    }

    __shared__ float red0[T / 32];
    __shared__ float red1[T / 32];
#pragma unroll
    for (int o = 16; o; o >>= 1) {
        s  += __shfl_xor_sync(0xffffffffu, s, o);
        ss += __shfl_xor_sync(0xffffffffu, ss, o);
    }
    if ((t & 31) == 0) { red0[t >> 5] = s; red1[t >> 5] = ss; }
    __syncthreads();
    if (t < 32) {
        float a = (t < T / 32) ? red0[t] : 0.f;
        float c = (t < T / 32) ? red1[t] : 0.f;
#pragma unroll
        for (int o = 4; o; o >>= 1) {
            a += __shfl_xor_sync(0xffffffffu, a, o);
            c += __shfl_xor_sync(0xffffffffu, c, o);
        }
        if (t == 0) { red0[0] = a; red1[0] = c; }
    }
    __syncthreads();
    const float m = red0[0] * (1.f / N);
    const float var = red1[0] * (1.f / N) - m * m;
    const float r = rsqrtf(var + 1e-5f);

#pragma unroll
    for (int i = 0; i < PER; i++) {
        const int j = t + i * T;
        const float v = (yv[i] - m) * r * g[j] + be[j];
        float o;
        if (ACT == 0) o = 0.5f * v * (1.f + erff(v * 0.70710678118654752f));
        else          o = v / (1.f + expf(-v));
        out[(long)row * N + j] = o;
    }
}

// ---------------------------------------------------------------------------
// Row LN + tanh, in place.  One block per row.
// ---------------------------------------------------------------------------
template<int N>
__global__ __launch_bounds__(256)
void ln_tanh_kernel(float* __restrict__ io,
                    const float* __restrict__ g,
                    const float* __restrict__ be) {
    constexpr int T = 256;
    constexpr int PER = N / T;
    const int row = blockIdx.x;
    const int t = threadIdx.x;
    float yv[PER];
    float s = 0.f, ss = 0.f;
#pragma unroll
    for (int i = 0; i < PER; i++) {
        const float y = io[(long)row * N + t + i * T];
        yv[i] = y; s += y; ss += y * y;
    }
    __shared__ float red0[T / 32];
    __shared__ float red1[T / 32];
#pragma unroll
    for (int o = 16; o; o >>= 1) {
        s  += __shfl_xor_sync(0xffffffffu, s, o);
        ss += __shfl_xor_sync(0xffffffffu, ss, o);
    }
    if ((t & 31) == 0) { red0[t >> 5] = s; red1[t >> 5] = ss; }
    __syncthreads();
    if (t < 32) {
        float a = (t < T / 32) ? red0[t] : 0.f;
        float c = (t < T / 32) ? red1[t] : 0.f;
#pragma unroll
        for (int o = 4; o; o >>= 1) {
            a += __shfl_xor_sync(0xffffffffu, a, o);
            c += __shfl_xor_sync(0xffffffffu, c, o);
        }
        if (t == 0) { red0[0] = a; red1[0] = c; }
    }
    __syncthreads();
    const float m = red0[0] * (1.f / N);
    const float var = red1[0] * (1.f / N) - m * m;
    const float r = rsqrtf(var + 1e-5f);
#pragma unroll
    for (int i = 0; i < PER; i++) {
        const int j = t + i * T;
        io[(long)row * N + j] = tanhf((yv[i] - m) * r * g[j] + be[j]);
    }
}

// ---------------------------------------------------------------------------
// GEMM: C[m][n] = sum_k A[m][k] * W[n][k] + bias[n]   (both K-major)
// 128x128 tile, BK=8, 256 threads, 8x8 per-thread microtile.
// EPI: 0 = bias only, 1 = bias + tanh
// M,N multiples of 128; K multiple of 8.
// ---------------------------------------------------------------------------
template<int EPI>
__global__ __launch_bounds__(256)
void gemm_nt_kernel(const float* __restrict__ A,
                    const float* __restrict__ Wt,
                    const float* __restrict__ bias,
                    float* __restrict__ C,
                    int M, int N, int K) {
    constexpr int BM = 128, BN = 128, BK = 8;
    __shared__ float As[BK][BM];
    __shared__ float Bs[BK][BN];

    const int bm = blockIdx.y * BM;
    const int bn = blockIdx.x * BN;
    const int t  = threadIdx.x;

    // global->smem load mapping: 2 float4 per row, one float4 per thread
    const int lr = t >> 1;           // 0..127
    const int lc = (t & 1) * 4;      // 0 or 4
    const float* Ag = A  + (long)(bm + lr) * K + lc;
    const float* Wg = Wt + (long)(bn + lr) * K + lc;

    // compute mapping: 16x16 threads, 8x8 each
    const int tr = (t >> 4) * 8;
    const int tc = (t & 15) * 8;

    float acc[8][8];
#pragma unroll
    for (int i = 0; i < 8; i++)
#pragma unroll
        for (int j = 0; j < 8; j++) acc[i][j] = 0.f;

    for (int k0 = 0; k0 < K; k0 += BK) {
        const float4 av = *(const float4*)(Ag + k0);
        const float4 wv = *(const float4*)(Wg + k0);
        As[lc + 0][lr] = av.x; As[lc + 1][lr] = av.y;
        As[lc + 2][lr] = av.z; As[lc + 3][lr] = av.w;
        Bs[lc + 0][lr] = wv.x; Bs[lc + 1][lr] = wv.y;
        Bs[lc + 2][lr] = wv.z; Bs[lc + 3][lr] = wv.w;
        __syncthreads();
#pragma unroll
        for (int k = 0; k < BK; k++) {
            float a[8], bfr[8];
#pragma unroll
            for (int i = 0; i < 8; i++) a[i] = As[k][tr + i];
#pragma unroll
            for (int j = 0; j < 8; j++) bfr[j] = Bs[k][tc + j];
#pragma unroll
            for (int i = 0; i < 8; i++)
#pragma unroll
                for (int j = 0; j < 8; j++)
                    acc[i][j] = fmaf(a[i], bfr[j], acc[i][j]);
        }
        __syncthreads();
    }

#pragma unroll
    for (int i = 0; i < 8; i++) {
        const long row = bm + tr + i;
#pragma unroll
        for (int j = 0; j < 8; j += 4) {
            const int col = bn + tc + j;
            float4 v;
            v.x = acc[i][j + 0] + bias[col + 0];
            v.y = acc[i][j + 1] + bias[col + 1];
            v.z = acc[i][j + 2] + bias[col + 2];
            v.w = acc[i][j + 3] + bias[col + 3];
            if (EPI == 1) {
                v.x = tanhf(v.x); v.y = tanhf(v.y);
                v.z = tanhf(v.z); v.w = tanhf(v.w);
            }
            *(float4*)(C + row * N + col) = v;
        }
    }
}

// ---------------------------------------------------------------------------
// qs = (sin(amp*f0+p0) + cos(phase*f1+p1) + tanh(p2)) / 3
// rot arrays are (D, Q, 3); we use slice D-1 = 4.
// ---------------------------------------------------------------------------
__global__ void qs_kernel(const float* __restrict__ amp,
                          const float* __restrict__ phase,
                          const float* __restrict__ rot_freq,
                          const float* __restrict__ rot_phase,
                          float* __restrict__ qs) {
    const int idx = blockIdx.x * blockDim.x + threadIdx.x;  // over B*Q
    const int j = idx & (QDIM - 1);
    const int base = (4 * QDIM + j) * 3;
    const float f0 = rot_freq[base + 0];
    const float f1 = rot_freq[base + 1];
    const float p0 = rot_phase[base + 0];
    const float p1 = rot_phase[base + 1];
    const float p2 = rot_phase[base + 2];
    const float rx = sinf(fmaf(amp[idx],   f0, p0));
    const float ry = cosf(fmaf(phase[idx], f1, p1));
    const float rz = tanhf(p2);
    qs[idx] = (rx + ry + rz) * (1.f / 3.f);
}

// ---------------------------------------------------------------------------
// Launch
// ---------------------------------------------------------------------------
extern "C" void kernel_launch(void* const* d_in, const int* in_sizes, int n_in,
                              void* d_out, int out_size) {
    const float* x        = (const float*)d_in[0];
    const float* amp_W1   = (const float*)d_in[1];
    const float* amp_b1   = (const float*)d_in[2];
    const float* amp_g1   = (const float*)d_in[3];
    const float* amp_be1  = (const float*)d_in[4];
    const float* amp_W2   = (const float*)d_in[5];
    const float* amp_b2   = (const float*)d_in[6];
    const float* amp_g2   = (const float*)d_in[7];
    const float* amp_be2  = (const float*)d_in[8];
    const float* amp_W3   = (const float*)d_in[9];
    const float* amp_b3   = (const float*)d_in[10];
    const float* ph_W1    = (const float*)d_in[11];
    const float* ph_b1    = (const float*)d_in[12];
    const float* ph_g1    = (const float*)d_in[13];
    const float* ph_be1   = (const float*)d_in[14];
    const float* ph_W2    = (const float*)d_in[15];
    const float* ph_b2    = (const float*)d_in[16];
    const float* rot_freq = (const float*)d_in[17];
    const float* rot_phase= (const float*)d_in[18];
    const float* attn_in_w= (const float*)d_in[19];
    const float* attn_in_b= (const float*)d_in[20];
    const float* attn_out_w=(const float*)d_in[21];
    const float* attn_out_b=(const float*)d_in[22];
    float* out = (float*)d_out;

    float *h1, *h2, *p, *amp, *phase, *qs, *v;
    cudaGetSymbolAddress((void**)&h1,    g_h1);
    cudaGetSymbolAddress((void**)&h2,    g_h2);
    cudaGetSymbolAddress((void**)&p,     g_p);
    cudaGetSymbolAddress((void**)&amp,   g_amp);
    cudaGetSymbolAddress((void**)&phase, g_phase);
    cudaGetSymbolAddress((void**)&qs,    g_qs);
    cudaGetSymbolAddress((void**)&v,     g_v);

    // amp path layer 1: x -> h1 (B x 4096), LN + gelu
    first_layer_kernel<4 * QDIM, 0><<<BROWS, 256>>>(x, amp_W1, amp_b1, amp_g1, amp_be1, h1);
    // ph path layer 1: x -> p (B x 2048), LN + silu
    first_layer_kernel<2 * QDIM, 1><<<BROWS, 256>>>(x, ph_W1, ph_b1, ph_g1, ph_be1, p);

    // h2pre = h1 @ W2^T + b2   (16384 x 2048, K=4096)
    {
        dim3 grid(2 * QDIM / 128, BROWS / 128);
        gemm_nt_kernel<0><<<grid, 256>>>(h1, amp_W2, amp_b2, h2, BROWS, 2 * QDIM, 4 * QDIM);
    }
    // h2 = tanh(LN(h2pre))
    ln_tanh_kernel<2 * QDIM><<<BROWS, 256>>>(h2, amp_g2, amp_be2);

    // amp = h2 @ W3^T + b3   (16384 x 1024, K=2048)
    {
        dim3 grid(QDIM / 128, BROWS / 128);
        gemm_nt_kernel<0><<<grid, 256>>>(h2, amp_W3, amp_b3, amp, BROWS, QDIM, 2 * QDIM);
    }
    // phase = tanh(p @ ph_W2^T + b2)   (16384 x 1024, K=2048)
    {
        dim3 grid(QDIM / 128, BROWS / 128);
        gemm_nt_kernel<1><<<grid, 256>>>(p, ph_W2, ph_b2, phase, BROWS, QDIM, 2 * QDIM);
    }

    // qs elementwise
    qs_kernel<<<(BROWS * QDIM) / 256, 256>>>(amp, phase, rot_freq, rot_phase, qs);

    // v = qs @ attn_in_w[2Q:3Q]^T + attn_in_b[2Q:]   (K=1024)
    {
        dim3 grid(QDIM / 128, BROWS / 128);
        gemm_nt_kernel<0><<<grid, 256>>>(qs, attn_in_w + (long)2 * QDIM * QDIM,
                                         attn_in_b + 2 * QDIM, v, BROWS, QDIM, QDIM);
    }
    // out = v @ attn_out_w^T + attn_out_b   (K=1024)
    {
        dim3 grid(QDIM / 128, BROWS / 128);
        gemm_nt_kernel<0><<<grid, 256>>>(v, attn_out_w, attn_out_b, out, BROWS, QDIM, QDIM);
    }
}

// round 6
// speedup vs baseline: 2.0336x; 2.0336x over previous
#include <cuda_runtime.h>
#include <cuda_bf16.h>
#include <math.h>
#include <stdint.h>

// Problem constants
#define BROWS 16384
#define QDIM  1024

// ---------------------------------------------------------------------------
// Scratch (static device globals)
// ---------------------------------------------------------------------------
__device__ __align__(16) __nv_bfloat16 g_h1h[BROWS * 4 * QDIM];
__device__ __align__(16) __nv_bfloat16 g_h1l[BROWS * 4 * QDIM];
__device__ __align__(16) __nv_bfloat16 g_ph [BROWS * 2 * QDIM];
__device__ __align__(16) __nv_bfloat16 g_pl [BROWS * 2 * QDIM];
__device__ __align__(16) float         g_h2f[BROWS * 2 * QDIM];
__device__ __align__(16) __nv_bfloat16 g_h2h[BROWS * 2 * QDIM];
__device__ __align__(16) __nv_bfloat16 g_h2l[BROWS * 2 * QDIM];
__device__ __align__(16) float         g_ampf  [BROWS * QDIM];
__device__ __align__(16) float         g_phasef[BROWS * QDIM];
__device__ __align__(16) __nv_bfloat16 g_qsh[BROWS * QDIM];
__device__ __align__(16) __nv_bfloat16 g_qsl[BROWS * QDIM];
__device__ __align__(16) __nv_bfloat16 g_vh [BROWS * QDIM];
__device__ __align__(16) __nv_bfloat16 g_vl [BROWS * QDIM];
// weights (hi/lo)
__device__ __align__(16) __nv_bfloat16 g_w2h [2 * QDIM * 4 * QDIM];
__device__ __align__(16) __nv_bfloat16 g_w2l [2 * QDIM * 4 * QDIM];
__device__ __align__(16) __nv_bfloat16 g_w3h [QDIM * 2 * QDIM];
__device__ __align__(16) __nv_bfloat16 g_w3l [QDIM * 2 * QDIM];
__device__ __align__(16) __nv_bfloat16 g_pw2h[QDIM * 2 * QDIM];
__device__ __align__(16) __nv_bfloat16 g_pw2l[QDIM * 2 * QDIM];
__device__ __align__(16) __nv_bfloat16 g_wvh [QDIM * QDIM];
__device__ __align__(16) __nv_bfloat16 g_wvl [QDIM * QDIM];
__device__ __align__(16) __nv_bfloat16 g_woh [QDIM * QDIM];
__device__ __align__(16) __nv_bfloat16 g_wol [QDIM * QDIM];

// ---------------------------------------------------------------------------
// sm_80-level PTX helpers only (cp.async, ldmatrix, mma.sync)
// ---------------------------------------------------------------------------
__device__ __forceinline__ uint32_t smem_u32(const void* p) {
    uint32_t a;
    asm("{ .reg .u64 t; cvta.to.shared.u64 t, %1; cvt.u32.u64 %0, t; }" : "=r"(a) : "l"(p));
    return a;
}
__device__ __forceinline__ void cp16(uint32_t s, const void* g) {
    asm volatile("cp.async.cg.shared.global [%0], [%1], 16;\n" :: "r"(s), "l"(g));
}
__device__ __forceinline__ void cp_commit() {
    asm volatile("cp.async.commit_group;\n" ::: "memory");
}
__device__ __forceinline__ void ldsm_x4(uint32_t* r, uint32_t addr) {
    asm volatile("ldmatrix.sync.aligned.m8n8.x4.shared.b16 {%0,%1,%2,%3}, [%4];"
        : "=r"(r[0]), "=r"(r[1]), "=r"(r[2]), "=r"(r[3]) : "r"(addr));
}
__device__ __forceinline__ void ldsm_x2(uint32_t* r, uint32_t addr) {
    asm volatile("ldmatrix.sync.aligned.m8n8.x2.shared.b16 {%0,%1}, [%2];"
        : "=r"(r[0]), "=r"(r[1]) : "r"(addr));
}
__device__ __forceinline__ void mma_bf16(float* c, const uint32_t* a, const uint32_t* b) {
    asm volatile(
        "mma.sync.aligned.m16n8k16.row.col.f32.bf16.bf16.f32 "
        "{%0,%1,%2,%3}, {%4,%5,%6,%7}, {%8,%9}, {%0,%1,%2,%3};"
        : "+f"(c[0]), "+f"(c[1]), "+f"(c[2]), "+f"(c[3])
        : "r"(a[0]), "r"(a[1]), "r"(a[2]), "r"(a[3]), "r"(b[0]), "r"(b[1]));
}
__device__ __forceinline__ void split2(float x, __nv_bfloat16& h, __nv_bfloat16& l) {
    h = __float2bfloat16(x);
    l = __float2bfloat16(x - __bfloat162float(h));
}

// ---------------------------------------------------------------------------
// Tensor-core GEMM via mma.sync (HMMA): C[m][n] = sum_k A[m][k]*B[n][k] + bias[n]
// A,B fp32 split into (hi,lo) bf16 K-major buffers; 3-way split accumulation.
// BM=128, BN=128, BK=32, 256 threads, warp tile 64x32, 2-stage cp.async pipe.
// EPI: 0 = fp32 out (+bias), 1 = bias+tanh fp32 out, 2 = split bf16 out
// ---------------------------------------------------------------------------
#define TCG_BM 128
#define TCG_BN 128
#define TCG_BK 32
// SMEM tile: 128 rows x 32 bf16, row padded to 80 bytes
#define ROWB 80u
#define TILE_BYTES (128u * ROWB)      // 10240
#define OFF_AH 0u
#define OFF_AL (TILE_BYTES)
#define OFF_BH (2u * TILE_BYTES)
#define OFF_BL (3u * TILE_BYTES)
#define STAGE_BYTES (4u * TILE_BYTES) // 40960

template<int EPI>
__global__ __launch_bounds__(256)
void tc_gemm(const __nv_bfloat16* __restrict__ Ah, const __nv_bfloat16* __restrict__ Al,
             const __nv_bfloat16* __restrict__ Bh, const __nv_bfloat16* __restrict__ Bl,
             const float* __restrict__ bias,
             float* __restrict__ Cf,
             __nv_bfloat16* __restrict__ Chi, __nv_bfloat16* __restrict__ Clo,
             int N, int K) {
    extern __shared__ char dynsmem[];
    const uint32_t sbase = smem_u32(dynsmem);
    const int t = threadIdx.x;
    const int wid = t >> 5;
    const int lane = t & 31;
    const int wm = wid & 1;        // 2 warps over M (64 each)
    const int wn = wid >> 1;       // 4 warps over N (32 each)
    const int bm = blockIdx.y * TCG_BM;
    const int bn = blockIdx.x * TCG_BN;

    float acc[4][4][4];
#pragma unroll
    for (int i = 0; i < 4; i++)
#pragma unroll
        for (int j = 0; j < 4; j++)
#pragma unroll
            for (int q = 0; q < 4; q++) acc[i][j][q] = 0.f;

    const int C = K / TCG_BK;

    auto load_chunk = [&](int c, int stg) {
        const int k0 = c * TCG_BK;
        const uint32_t base = sbase + stg * STAGE_BYTES;
#pragma unroll
        for (int i = 0; i < 2; i++) {
            const int idx = t + i * 256;          // 0..511
            const int row = idx >> 2, cc = idx & 3;
            const uint32_t so = (uint32_t)row * ROWB + cc * 16;
            const size_t gA = (size_t)(bm + row) * K + k0 + cc * 8;
            const size_t gB = (size_t)(bn + row) * K + k0 + cc * 8;
            cp16(base + OFF_AH + so, Ah + gA);
            cp16(base + OFF_AL + so, Al + gA);
            cp16(base + OFF_BH + so, Bh + gB);
            cp16(base + OFF_BL + so, Bl + gB);
        }
        cp_commit();
    };

    // ldmatrix lane->address components (constant over loop)
    const int a_row = wm * 64 + (lane & 15);
    const int a_colh = (lane >> 4) * 8;           // 0 or 8 (k halves)
    const int b_row = wn * 32 + (lane & 7);
    const int b_colh = ((lane >> 3) & 1) * 8;

    load_chunk(0, 0);

    for (int c = 0; c < C; ++c) {
        const int s = c & 1;
        if (c + 1 < C) {
            load_chunk(c + 1, s ^ 1);
            asm volatile("cp.async.wait_group 1;\n" ::: "memory");
        } else {
            asm volatile("cp.async.wait_group 0;\n" ::: "memory");
        }
        __syncthreads();

        const uint32_t base = sbase + s * STAGE_BYTES;
#pragma unroll
        for (int ks = 0; ks < 2; ks++) {
            const int kof = ks * 16;
            uint32_t ah[4][4], al[4][4], bh[4][2], bl[4][2];
#pragma unroll
            for (int fm = 0; fm < 4; fm++) {
                const uint32_t off = (uint32_t)(a_row + fm * 16) * ROWB + (kof + a_colh) * 2;
                ldsm_x4(ah[fm], base + OFF_AH + off);
                ldsm_x4(al[fm], base + OFF_AL + off);
            }
#pragma unroll
            for (int fn = 0; fn < 4; fn++) {
                const uint32_t off = (uint32_t)(b_row + fn * 8) * ROWB + (kof + b_colh) * 2;
                ldsm_x2(bh[fn], base + OFF_BH + off);
                ldsm_x2(bl[fn], base + OFF_BL + off);
            }
#pragma unroll
            for (int fm = 0; fm < 4; fm++)
#pragma unroll
                for (int fn = 0; fn < 4; fn++) {
                    mma_bf16(acc[fm][fn], ah[fm], bh[fn]);
                    mma_bf16(acc[fm][fn], ah[fm], bl[fn]);
                    mma_bf16(acc[fm][fn], al[fm], bh[fn]);
                }
        }
        __syncthreads();
    }

    // ---- epilogue ----
    const int row0 = bm + wm * 64 + (lane >> 2);
    const int colb = bn + wn * 32 + (lane & 3) * 2;
#pragma unroll
    for (int fm = 0; fm < 4; fm++) {
        const long r0 = row0 + fm * 16;
        const long r1 = r0 + 8;
#pragma unroll
        for (int fn = 0; fn < 4; fn++) {
            const int col = colb + fn * 8;
            const float b0 = bias[col], b1 = bias[col + 1];
            float y00 = acc[fm][fn][0] + b0;
            float y01 = acc[fm][fn][1] + b1;
            float y10 = acc[fm][fn][2] + b0;
            float y11 = acc[fm][fn][3] + b1;
            if (EPI == 1) {
                y00 = tanhf(y00); y01 = tanhf(y01);
                y10 = tanhf(y10); y11 = tanhf(y11);
            }
            if (EPI == 0 || EPI == 1) {
                *(float2*)(Cf + r0 * N + col) = make_float2(y00, y01);
                *(float2*)(Cf + r1 * N + col) = make_float2(y10, y11);
            } else {
                __nv_bfloat16 h0, l0, h1, l1;
                __nv_bfloat162 hv, lv;
                split2(y00, h0, l0); split2(y01, h1, l1);
                hv.x = h0; hv.y = h1; lv.x = l0; lv.y = l1;
                *(__nv_bfloat162*)(Chi + r0 * N + col) = hv;
                *(__nv_bfloat162*)(Clo + r0 * N + col) = lv;
                split2(y10, h0, l0); split2(y11, h1, l1);
                hv.x = h0; hv.y = h1; lv.x = l0; lv.y = l1;
                *(__nv_bfloat162*)(Chi + r1 * N + col) = hv;
                *(__nv_bfloat162*)(Clo + r1 * N + col) = lv;
            }
        }
    }
}

// ---------------------------------------------------------------------------
// Weight split: fp32 -> (hi, lo) bf16
// ---------------------------------------------------------------------------
__global__ void split_kernel(const float* __restrict__ src,
                             __nv_bfloat16* __restrict__ hi,
                             __nv_bfloat16* __restrict__ lo, int n) {
    const int i = blockIdx.x * 256 + threadIdx.x;
    if (i < n) {
        __nv_bfloat16 h, l;
        split2(src[i], h, l);
        hi[i] = h; lo[i] = l;
    }
}

// ---------------------------------------------------------------------------
// First layer: y = x @ W^T + b (K=2), LN, activation, split-bf16 out.
// ACT: 0 = exact gelu, 1 = silu
// ---------------------------------------------------------------------------
template<int N, int ACT>
__global__ __launch_bounds__(256)
void first_layer_kernel(const float* __restrict__ x,
                        const float* __restrict__ W,
                        const float* __restrict__ b,
                        const float* __restrict__ g,
                        const float* __restrict__ be,
                        __nv_bfloat16* __restrict__ outh,
                        __nv_bfloat16* __restrict__ outl) {
    constexpr int T = 256;
    constexpr int PER = N / T;
    const int row = blockIdx.x;
    const int t = threadIdx.x;
    const float x0 = x[row * 2 + 0];
    const float x1 = x[row * 2 + 1];

    float yv[PER];
    float s = 0.f, ss = 0.f;
#pragma unroll
    for (int i = 0; i < PER; i++) {
        const int j = t + i * T;
        const float y = fmaf(x0, W[2 * j], fmaf(x1, W[2 * j + 1], b[j]));
        yv[i] = y; s += y; ss += y * y;
    }
    __shared__ float red0[T / 32];
    __shared__ float red1[T / 32];
#pragma unroll
    for (int o = 16; o; o >>= 1) {
        s  += __shfl_xor_sync(0xffffffffu, s, o);
        ss += __shfl_xor_sync(0xffffffffu, ss, o);
    }
    if ((t & 31) == 0) { red0[t >> 5] = s; red1[t >> 5] = ss; }
    __syncthreads();
    if (t < 32) {
        float a = (t < T / 32) ? red0[t] : 0.f;
        float c = (t < T / 32) ? red1[t] : 0.f;
#pragma unroll
        for (int o = 4; o; o >>= 1) {
            a += __shfl_xor_sync(0xffffffffu, a, o);
            c += __shfl_xor_sync(0xffffffffu, c, o);
        }
        if (t == 0) { red0[0] = a; red1[0] = c; }
    }
    __syncthreads();
    const float m = red0[0] * (1.f / N);
    const float var = red1[0] * (1.f / N) - m * m;
    const float r = rsqrtf(var + 1e-5f);
#pragma unroll
    for (int i = 0; i < PER; i++) {
        const int j = t + i * T;
        const float v = (yv[i] - m) * r * g[j] + be[j];
        float o;
        if (ACT == 0) o = 0.5f * v * (1.f + erff(v * 0.70710678118654752f));
        else          o = v / (1.f + expf(-v));
        __nv_bfloat16 h, l;
        split2(o, h, l);
        outh[(long)row * N + j] = h;
        outl[(long)row * N + j] = l;
    }
}

// ---------------------------------------------------------------------------
// LN + tanh: fp32 in, split bf16 out
// ---------------------------------------------------------------------------
template<int N>
__global__ __launch_bounds__(256)
void ln_tanh_split_kernel(const float* __restrict__ in,
                          const float* __restrict__ g,
                          const float* __restrict__ be,
                          __nv_bfloat16* __restrict__ outh,
                          __nv_bfloat16* __restrict__ outl) {
    constexpr int T = 256;
    constexpr int PER = N / T;
    const int row = blockIdx.x;
    const int t = threadIdx.x;
    float yv[PER];
    float s = 0.f, ss = 0.f;
#pragma unroll
    for (int i = 0; i < PER; i++) {
        const float y = in[(long)row * N + t + i * T];
        yv[i] = y; s += y; ss += y * y;
    }
    __shared__ float red0[T / 32];
    __shared__ float red1[T / 32];
#pragma unroll
    for (int o = 16; o; o >>= 1) {
        s  += __shfl_xor_sync(0xffffffffu, s, o);
        ss += __shfl_xor_sync(0xffffffffu, ss, o);
    }
    if ((t & 31) == 0) { red0[t >> 5] = s; red1[t >> 5] = ss; }
    __syncthreads();
    if (t < 32) {
        float a = (t < T / 32) ? red0[t] : 0.f;
        float c = (t < T / 32) ? red1[t] : 0.f;
#pragma unroll
        for (int o = 4; o; o >>= 1) {
            a += __shfl_xor_sync(0xffffffffu, a, o);
            c += __shfl_xor_sync(0xffffffffu, c, o);
        }
        if (t == 0) { red0[0] = a; red1[0] = c; }
    }
    __syncthreads();
    const float m = red0[0] * (1.f / N);
    const float var = red1[0] * (1.f / N) - m * m;
    const float r = rsqrtf(var + 1e-5f);
#pragma unroll
    for (int i = 0; i < PER; i++) {
        const int j = t + i * T;
        const float y = tanhf((yv[i] - m) * r * g[j] + be[j]);
        __nv_bfloat16 h, l;
        split2(y, h, l);
        outh[(long)row * N + j] = h;
        outl[(long)row * N + j] = l;
    }
}

// ---------------------------------------------------------------------------
// qs = (sin(amp*f0+p0) + cos(phase*f1+p1) + tanh(p2)) / 3, split-bf16 out
// ---------------------------------------------------------------------------
__global__ void qs_kernel(const float* __restrict__ amp,
                          const float* __restrict__ phase,
                          const float* __restrict__ rot_freq,
                          const float* __restrict__ rot_phase,
                          __nv_bfloat16* __restrict__ qsh,
                          __nv_bfloat16* __restrict__ qsl) {
    const int idx = blockIdx.x * blockDim.x + threadIdx.x;
    const int j = idx & (QDIM - 1);
    const int base = (4 * QDIM + j) * 3;
    const float f0 = rot_freq[base + 0];
    const float f1 = rot_freq[base + 1];
    const float p0 = rot_phase[base + 0];
    const float p1 = rot_phase[base + 1];
    const float p2 = rot_phase[base + 2];
    const float rx = sinf(fmaf(amp[idx],   f0, p0));
    const float ry = cosf(fmaf(phase[idx], f1, p1));
    const float rz = tanhf(p2);
    __nv_bfloat16 h, l;
    split2((rx + ry + rz) * (1.f / 3.f), h, l);
    qsh[idx] = h; qsl[idx] = l;
}

// ---------------------------------------------------------------------------
// Launch
// ---------------------------------------------------------------------------
extern "C" void kernel_launch(void* const* d_in, const int* in_sizes, int n_in,
                              void* d_out, int out_size) {
    const float* x        = (const float*)d_in[0];
    const float* amp_W1   = (const float*)d_in[1];
    const float* amp_b1   = (const float*)d_in[2];
    const float* amp_g1   = (const float*)d_in[3];
    const float* amp_be1  = (const float*)d_in[4];
    const float* amp_W2   = (const float*)d_in[5];
    const float* amp_b2   = (const float*)d_in[6];
    const float* amp_g2   = (const float*)d_in[7];
    const float* amp_be2  = (const float*)d_in[8];
    const float* amp_W3   = (const float*)d_in[9];
    const float* amp_b3   = (const float*)d_in[10];
    const float* ph_W1    = (const float*)d_in[11];
    const float* ph_b1    = (const float*)d_in[12];
    const float* ph_g1    = (const float*)d_in[13];
    const float* ph_be1   = (const float*)d_in[14];
    const float* ph_W2    = (const float*)d_in[15];
    const float* ph_b2    = (const float*)d_in[16];
    const float* rot_freq = (const float*)d_in[17];
    const float* rot_phase= (const float*)d_in[18];
    const float* attn_in_w= (const float*)d_in[19];
    const float* attn_in_b= (const float*)d_in[20];
    const float* attn_out_w=(const float*)d_in[21];
    const float* attn_out_b=(const float*)d_in[22];
    float* out = (float*)d_out;

    __nv_bfloat16 *h1h, *h1l, *ph, *pl, *h2h, *h2l, *qsh, *qsl, *vh, *vl;
    __nv_bfloat16 *w2h, *w2l, *w3h, *w3l, *pw2h, *pw2l, *wvh, *wvl, *woh, *wol;
    float *h2f, *ampf, *phasef;
    cudaGetSymbolAddress((void**)&h1h, g_h1h);  cudaGetSymbolAddress((void**)&h1l, g_h1l);
    cudaGetSymbolAddress((void**)&ph,  g_ph);   cudaGetSymbolAddress((void**)&pl,  g_pl);
    cudaGetSymbolAddress((void**)&h2f, g_h2f);
    cudaGetSymbolAddress((void**)&h2h, g_h2h);  cudaGetSymbolAddress((void**)&h2l, g_h2l);
    cudaGetSymbolAddress((void**)&ampf, g_ampf);
    cudaGetSymbolAddress((void**)&phasef, g_phasef);
    cudaGetSymbolAddress((void**)&qsh, g_qsh);  cudaGetSymbolAddress((void**)&qsl, g_qsl);
    cudaGetSymbolAddress((void**)&vh,  g_vh);   cudaGetSymbolAddress((void**)&vl,  g_vl);
    cudaGetSymbolAddress((void**)&w2h, g_w2h);  cudaGetSymbolAddress((void**)&w2l, g_w2l);
    cudaGetSymbolAddress((void**)&w3h, g_w3h);  cudaGetSymbolAddress((void**)&w3l, g_w3l);
    cudaGetSymbolAddress((void**)&pw2h, g_pw2h); cudaGetSymbolAddress((void**)&pw2l, g_pw2l);
    cudaGetSymbolAddress((void**)&wvh, g_wvh);  cudaGetSymbolAddress((void**)&wvl, g_wvl);
    cudaGetSymbolAddress((void**)&woh, g_woh);  cudaGetSymbolAddress((void**)&wol, g_wol);

    static bool attr_done = false;
    if (!attr_done) {
        cudaFuncSetAttribute(tc_gemm<0>, cudaFuncAttributeMaxDynamicSharedMemorySize, 2 * STAGE_BYTES);
        cudaFuncSetAttribute(tc_gemm<1>, cudaFuncAttributeMaxDynamicSharedMemorySize, 2 * STAGE_BYTES);
        cudaFuncSetAttribute(tc_gemm<2>, cudaFuncAttributeMaxDynamicSharedMemorySize, 2 * STAGE_BYTES);
        attr_done = true;
    }
    const size_t dsm = 2 * STAGE_BYTES;

    // Weight splits
    {
        int n;
        n = 2 * QDIM * 4 * QDIM; split_kernel<<<(n + 255) / 256, 256>>>(amp_W2, w2h, w2l, n);
        n = QDIM * 2 * QDIM;     split_kernel<<<(n + 255) / 256, 256>>>(amp_W3, w3h, w3l, n);
        n = QDIM * 2 * QDIM;     split_kernel<<<(n + 255) / 256, 256>>>(ph_W2,  pw2h, pw2l, n);
        n = QDIM * QDIM;         split_kernel<<<(n + 255) / 256, 256>>>(attn_in_w + (long)2 * QDIM * QDIM, wvh, wvl, n);
        n = QDIM * QDIM;         split_kernel<<<(n + 255) / 256, 256>>>(attn_out_w, woh, wol, n);
    }

    // amp layer 1: x -> h1 split (B x 4096), LN + gelu
    first_layer_kernel<4 * QDIM, 0><<<BROWS, 256>>>(x, amp_W1, amp_b1, amp_g1, amp_be1, h1h, h1l);
    // ph layer 1: x -> p split (B x 2048), LN + silu
    first_layer_kernel<2 * QDIM, 1><<<BROWS, 256>>>(x, ph_W1, ph_b1, ph_g1, ph_be1, ph, pl);

    // h2pre = h1 @ W2^T + b2  (16384 x 2048, K=4096), fp32 out
    {
        dim3 grid(2 * QDIM / TCG_BN, BROWS / TCG_BM);
        tc_gemm<0><<<grid, 256, dsm>>>(h1h, h1l, w2h, w2l, amp_b2, h2f, nullptr, nullptr, 2 * QDIM, 4 * QDIM);
    }
    // h2 = tanh(LN(h2pre)), split out
    ln_tanh_split_kernel<2 * QDIM><<<BROWS, 256>>>(h2f, amp_g2, amp_be2, h2h, h2l);

    // amp = h2 @ W3^T + b3  (16384 x 1024, K=2048), fp32 out
    {
        dim3 grid(QDIM / TCG_BN, BROWS / TCG_BM);
        tc_gemm<0><<<grid, 256, dsm>>>(h2h, h2l, w3h, w3l, amp_b3, ampf, nullptr, nullptr, QDIM, 2 * QDIM);
    }
    // phase = tanh(p @ ph_W2^T + b2)  (16384 x 1024, K=2048)
    {
        dim3 grid(QDIM / TCG_BN, BROWS / TCG_BM);
        tc_gemm<1><<<grid, 256, dsm>>>(ph, pl, pw2h, pw2l, ph_b2, phasef, nullptr, nullptr, QDIM, 2 * QDIM);
    }

    // qs elementwise, split out
    qs_kernel<<<(BROWS * QDIM) / 256, 256>>>(ampf, phasef, rot_freq, rot_phase, qsh, qsl);

    // v = qs @ Wv^T + bv  (K=1024), split out
    {
        dim3 grid(QDIM / TCG_BN, BROWS / TCG_BM);
        tc_gemm<2><<<grid, 256, dsm>>>(qsh, qsl, wvh, wvl, attn_in_b + 2 * QDIM, nullptr, vh, vl, QDIM, QDIM);
    }
    // out = v @ Wo^T + bo  (K=1024), fp32 out
    {
        dim3 grid(QDIM / TCG_BN, BROWS / TCG_BM);
        tc_gemm<0><<<grid, 256, dsm>>>(vh, vl, woh, wol, attn_out_b, out, nullptr, nullptr, QDIM, QDIM);
    }
}

// round 11
// speedup vs baseline: 2.8173x; 1.3854x over previous
#include <cuda_runtime.h>
#include <cuda_bf16.h>
#include <math.h>
#include <stdint.h>

// Problem constants
#define BROWS 16384
#define QDIM  1024

// ---------------------------------------------------------------------------
// Scratch (static device globals)
// ---------------------------------------------------------------------------
__device__ __align__(16) __nv_bfloat16 g_h1h[BROWS * 4 * QDIM];
__device__ __align__(16) __nv_bfloat16 g_h1l[BROWS * 4 * QDIM];
__device__ __align__(16) __nv_bfloat16 g_ph [BROWS * 2 * QDIM];
__device__ __align__(16) __nv_bfloat16 g_pl [BROWS * 2 * QDIM];
__device__ __align__(16) float         g_h2f[BROWS * 2 * QDIM];
__device__ __align__(16) __nv_bfloat16 g_h2h[BROWS * 2 * QDIM];
__device__ __align__(16) __nv_bfloat16 g_h2l[BROWS * 2 * QDIM];
__device__ __align__(16) float         g_ampf  [BROWS * QDIM];
__device__ __align__(16) float         g_phasef[BROWS * QDIM];
__device__ __align__(16) __nv_bfloat16 g_qsh[BROWS * QDIM];
__device__ __align__(16) __nv_bfloat16 g_qsl[BROWS * QDIM];
__device__ __align__(16) __nv_bfloat16 g_vh [BROWS * QDIM];
__device__ __align__(16) __nv_bfloat16 g_vl [BROWS * QDIM];
// weights (hi/lo)
__device__ __align__(16) __nv_bfloat16 g_w2h [2 * QDIM * 4 * QDIM];
__device__ __align__(16) __nv_bfloat16 g_w2l [2 * QDIM * 4 * QDIM];
__device__ __align__(16) __nv_bfloat16 g_w3h [QDIM * 2 * QDIM];
__device__ __align__(16) __nv_bfloat16 g_w3l [QDIM * 2 * QDIM];
__device__ __align__(16) __nv_bfloat16 g_pw2h[QDIM * 2 * QDIM];
__device__ __align__(16) __nv_bfloat16 g_pw2l[QDIM * 2 * QDIM];
__device__ __align__(16) __nv_bfloat16 g_wvh [QDIM * QDIM];
__device__ __align__(16) __nv_bfloat16 g_wvl [QDIM * QDIM];
__device__ __align__(16) __nv_bfloat16 g_woh [QDIM * QDIM];
__device__ __align__(16) __nv_bfloat16 g_wol [QDIM * QDIM];

// ---------------------------------------------------------------------------
// sm_80-level PTX helpers only (cp.async, ldmatrix, mma.sync)
// ---------------------------------------------------------------------------
__device__ __forceinline__ uint32_t smem_u32(const void* p) {
    uint32_t a;
    asm("{ .reg .u64 t; cvta.to.shared.u64 t, %1; cvt.u32.u64 %0, t; }" : "=r"(a) : "l"(p));
    return a;
}
__device__ __forceinline__ void cp16(uint32_t s, const void* g) {
    asm volatile("cp.async.cg.shared.global [%0], [%1], 16;\n" :: "r"(s), "l"(g));
}
__device__ __forceinline__ void cp_commit() {
    asm volatile("cp.async.commit_group;\n" ::: "memory");
}
__device__ __forceinline__ void ldsm_x4(uint32_t* r, uint32_t addr) {
    asm volatile("ldmatrix.sync.aligned.m8n8.x4.shared.b16 {%0,%1,%2,%3}, [%4];"
        : "=r"(r[0]), "=r"(r[1]), "=r"(r[2]), "=r"(r[3]) : "r"(addr));
}
__device__ __forceinline__ void ldsm_x2(uint32_t* r, uint32_t addr) {
    asm volatile("ldmatrix.sync.aligned.m8n8.x2.shared.b16 {%0,%1}, [%2];"
        : "=r"(r[0]), "=r"(r[1]) : "r"(addr));
}
__device__ __forceinline__ void mma_bf16(float* c, const uint32_t* a, const uint32_t* b) {
    asm volatile(
        "mma.sync.aligned.m16n8k16.row.col.f32.bf16.bf16.f32 "
        "{%0,%1,%2,%3}, {%4,%5,%6,%7}, {%8,%9}, {%0,%1,%2,%3};"
        : "+f"(c[0]), "+f"(c[1]), "+f"(c[2]), "+f"(c[3])
        : "r"(a[0]), "r"(a[1]), "r"(a[2]), "r"(a[3]), "r"(b[0]), "r"(b[1]));
}
__device__ __forceinline__ void split2(float x, __nv_bfloat16& h, __nv_bfloat16& l) {
    h = __float2bfloat16(x);
    l = __float2bfloat16(x - __bfloat162float(h));
}

// ---------------------------------------------------------------------------
// Tensor-core GEMM via mma.sync (HMMA): C[m][n] = sum_k A[m][k]*B[n][k] + bias[n]
// A,B fp32 split into (hi,lo) bf16 K-major buffers; 3-way split accumulation.
// BM=128, BN=128, BK=64, 256 threads, warp tile 64x32, 2-stage cp.async pipe.
// Split-term loop is OUTERMOST within each k-step so consecutive HMMAs never
// share an accumulator.
// EPI: 0 = fp32 out (+bias), 1 = bias+tanh fp32 out, 2 = split bf16 out
// ---------------------------------------------------------------------------
#define TCG_BM 128
#define TCG_BN 128
#define TCG_BK 64
// SMEM tile: 128 rows x 64 bf16 (128B), padded to 144B/row (conflict-free ldsm)
#define ROWB 144u
#define TILE_BYTES (128u * ROWB)      // 18432
#define OFF_AH 0u
#define OFF_AL (TILE_BYTES)
#define OFF_BH (2u * TILE_BYTES)
#define OFF_BL (3u * TILE_BYTES)
#define STAGE_BYTES (4u * TILE_BYTES) // 73728

template<int EPI>
__global__ __launch_bounds__(256)
void tc_gemm(const __nv_bfloat16* __restrict__ Ah, const __nv_bfloat16* __restrict__ Al,
             const __nv_bfloat16* __restrict__ Bh, const __nv_bfloat16* __restrict__ Bl,
             const float* __restrict__ bias,
             float* __restrict__ Cf,
             __nv_bfloat16* __restrict__ Chi, __nv_bfloat16* __restrict__ Clo,
             int N, int K) {
    extern __shared__ char dynsmem[];
    const uint32_t sbase = smem_u32(dynsmem);
    const int t = threadIdx.x;
    const int wid = t >> 5;
    const int lane = t & 31;
    const int wm = wid & 1;        // 2 warps over M (64 each)
    const int wn = wid >> 1;       // 4 warps over N (32 each)
    const int bm = blockIdx.y * TCG_BM;
    const int bn = blockIdx.x * TCG_BN;

    float acc[4][4][4];
#pragma unroll
    for (int i = 0; i < 4; i++)
#pragma unroll
        for (int j = 0; j < 4; j++)
#pragma unroll
            for (int q = 0; q < 4; q++) acc[i][j][q] = 0.f;

    const int C = K / TCG_BK;

    // Tile row = 64 bf16 = 128 bytes = 8 x 16B chunks.
    // 128 rows x 8 chunks = 1024 chunks per tile; 256 threads x 4 iters.
    // SMEM offset cc*16 BYTES <-> global offset cc*8 ELEMENTS (bijective).
    auto load_chunk = [&](int c, int stg) {
        const int k0 = c * TCG_BK;
        const uint32_t base = sbase + stg * STAGE_BYTES;
#pragma unroll
        for (int i = 0; i < 4; i++) {
            const int idx = t + i * 256;          // 0..1023
            const int row = idx >> 3, cc = idx & 7;
            const uint32_t so = (uint32_t)row * ROWB + cc * 16;
            const size_t gA = (size_t)(bm + row) * K + k0 + cc * 8;
            const size_t gB = (size_t)(bn + row) * K + k0 + cc * 8;
            cp16(base + OFF_AH + so, Ah + gA);
            cp16(base + OFF_AL + so, Al + gA);
            cp16(base + OFF_BH + so, Bh + gB);
            cp16(base + OFF_BL + so, Bl + gB);
        }
        cp_commit();
    };

    // ldmatrix lane->address components (constant over loop)
    const int a_row = wm * 64 + (lane & 15);
    const int a_colh = (lane >> 4) * 8;           // 0 or 8 (k halves)
    const int b_row = wn * 32 + (lane & 7);
    const int b_colh = ((lane >> 3) & 1) * 8;

    load_chunk(0, 0);

    for (int c = 0; c < C; ++c) {
        const int s = c & 1;
        if (c + 1 < C) {
            load_chunk(c + 1, s ^ 1);
            asm volatile("cp.async.wait_group 1;\n" ::: "memory");
        } else {
            asm volatile("cp.async.wait_group 0;\n" ::: "memory");
        }
        __syncthreads();

        const uint32_t base = sbase + s * STAGE_BYTES;
#pragma unroll
        for (int ks = 0; ks < 4; ks++) {
            const int kof = ks * 16;
            uint32_t ah[4][4], al[4][4], bh[4][2], bl[4][2];
#pragma unroll
            for (int fm = 0; fm < 4; fm++) {
                const uint32_t off = (uint32_t)(a_row + fm * 16) * ROWB + (kof + a_colh) * 2;
                ldsm_x4(ah[fm], base + OFF_AH + off);
                ldsm_x4(al[fm], base + OFF_AL + off);
            }
#pragma unroll
            for (int fn = 0; fn < 4; fn++) {
                const uint32_t off = (uint32_t)(b_row + fn * 8) * ROWB + (kof + b_colh) * 2;
                ldsm_x2(bh[fn], base + OFF_BH + off);
                ldsm_x2(bl[fn], base + OFF_BL + off);
            }
            // split term OUTERMOST: same acc is 16 mmas apart, no RAW stalls
#pragma unroll
            for (int fm = 0; fm < 4; fm++)
#pragma unroll
                for (int fn = 0; fn < 4; fn++)
                    mma_bf16(acc[fm][fn], ah[fm], bh[fn]);
#pragma unroll
            for (int fm = 0; fm < 4; fm++)
#pragma unroll
                for (int fn = 0; fn < 4; fn++)
                    mma_bf16(acc[fm][fn], ah[fm], bl[fn]);
#pragma unroll
            for (int fm = 0; fm < 4; fm++)
#pragma unroll
                for (int fn = 0; fn < 4; fn++)
                    mma_bf16(acc[fm][fn], al[fm], bh[fn]);
        }
        __syncthreads();
    }

    // ---- epilogue ----
    const int row0 = bm + wm * 64 + (lane >> 2);
    const int colb = bn + wn * 32 + (lane & 3) * 2;
#pragma unroll
    for (int fm = 0; fm < 4; fm++) {
        const long r0 = row0 + fm * 16;
        const long r1 = r0 + 8;
#pragma unroll
        for (int fn = 0; fn < 4; fn++) {
            const int col = colb + fn * 8;
            const float b0 = bias[col], b1 = bias[col + 1];
            float y00 = acc[fm][fn][0] + b0;
            float y01 = acc[fm][fn][1] + b1;
            float y10 = acc[fm][fn][2] + b0;
            float y11 = acc[fm][fn][3] + b1;
            if (EPI == 1) {
                y00 = tanhf(y00); y01 = tanhf(y01);
                y10 = tanhf(y10); y11 = tanhf(y11);
            }
            if (EPI == 0 || EPI == 1) {
                *(float2*)(Cf + r0 * N + col) = make_float2(y00, y01);
                *(float2*)(Cf + r1 * N + col) = make_float2(y10, y11);
            } else {
                __nv_bfloat16 h0, l0, h1, l1;
                __nv_bfloat162 hv, lv;
                split2(y00, h0, l0); split2(y01, h1, l1);
                hv.x = h0; hv.y = h1; lv.x = l0; lv.y = l1;
                *(__nv_bfloat162*)(Chi + r0 * N + col) = hv;
                *(__nv_bfloat162*)(Clo + r0 * N + col) = lv;
                split2(y10, h0, l0); split2(y11, h1, l1);
                hv.x = h0; hv.y = h1; lv.x = l0; lv.y = l1;
                *(__nv_bfloat162*)(Chi + r1 * N + col) = hv;
                *(__nv_bfloat162*)(Clo + r1 * N + col) = lv;
            }
        }
    }
}

// ---------------------------------------------------------------------------
// Weight split: fp32 -> (hi, lo) bf16
// ---------------------------------------------------------------------------
__global__ void split_kernel(const float* __restrict__ src,
                             __nv_bfloat16* __restrict__ hi,
                             __nv_bfloat16* __restrict__ lo, int n) {
    const int i = blockIdx.x * 256 + threadIdx.x;
    if (i < n) {
        __nv_bfloat16 h, l;
        split2(src[i], h, l);
        hi[i] = h; lo[i] = l;
    }
}

// ---------------------------------------------------------------------------
// First layer: y = x @ W^T + b (K=2), LN, activation, split-bf16 out.
// ACT: 0 = exact gelu, 1 = silu
// ---------------------------------------------------------------------------
template<int N, int ACT>
__global__ __launch_bounds__(256)
void first_layer_kernel(const float* __restrict__ x,
                        const float* __restrict__ W,
                        const float* __restrict__ b,
                        const float* __restrict__ g,
                        const float* __restrict__ be,
                        __nv_bfloat16* __restrict__ outh,
                        __nv_bfloat16* __restrict__ outl) {
    constexpr int T = 256;
    constexpr int PER = N / T;
    const int row = blockIdx.x;
    const int t = threadIdx.x;
    const float x0 = x[row * 2 + 0];
    const float x1 = x[row * 2 + 1];

    float yv[PER];
    float s = 0.f, ss = 0.f;
#pragma unroll
    for (int i = 0; i < PER; i++) {
        const int j = t + i * T;
        const float y = fmaf(x0, W[2 * j], fmaf(x1, W[2 * j + 1], b[j]));
        yv[i] = y; s += y; ss += y * y;
    }
    __shared__ float red0[T / 32];
    __shared__ float red1[T / 32];
#pragma unroll
    for (int o = 16; o; o >>= 1) {
        s  += __shfl_xor_sync(0xffffffffu, s, o);
        ss += __shfl_xor_sync(0xffffffffu, ss, o);
    }
    if ((t & 31) == 0) { red0[t >> 5] = s; red1[t >> 5] = ss; }
    __syncthreads();
    if (t < 32) {
        float a = (t < T / 32) ? red0[t] : 0.f;
        float c = (t < T / 32) ? red1[t] : 0.f;
#pragma unroll
        for (int o = 4; o; o >>= 1) {
            a += __shfl_xor_sync(0xffffffffu, a, o);
            c += __shfl_xor_sync(0xffffffffu, c, o);
        }
        if (t == 0) { red0[0] = a; red1[0] = c; }
    }
    __syncthreads();
    const float m = red0[0] * (1.f / N);
    const float var = red1[0] * (1.f / N) - m * m;
    const float r = rsqrtf(var + 1e-5f);
#pragma unroll
    for (int i = 0; i < PER; i++) {
        const int j = t + i * T;
        const float v = (yv[i] - m) * r * g[j] + be[j];
        float o;
        if (ACT == 0) o = 0.5f * v * (1.f + erff(v * 0.70710678118654752f));
        else          o = v / (1.f + expf(-v));
        __nv_bfloat16 h, l;
        split2(o, h, l);
        outh[(long)row * N + j] = h;
        outl[(long)row * N + j] = l;
    }
}

// ---------------------------------------------------------------------------
// LN + tanh: fp32 in, split bf16 out
// ---------------------------------------------------------------------------
template<int N>
__global__ __launch_bounds__(256)
void ln_tanh_split_kernel(const float* __restrict__ in,
                          const float* __restrict__ g,
                          const float* __restrict__ be,
                          __nv_bfloat16* __restrict__ outh,
                          __nv_bfloat16* __restrict__ outl) {
    constexpr int T = 256;
    constexpr int PER = N / T;
    const int row = blockIdx.x;
    const int t = threadIdx.x;
    float yv[PER];
    float s = 0.f, ss = 0.f;
#pragma unroll
    for (int i = 0; i < PER; i++) {
        const float y = in[(long)row * N + t + i * T];
        yv[i] = y; s += y; ss += y * y;
    }
    __shared__ float red0[T / 32];
    __shared__ float red1[T / 32];
#pragma unroll
    for (int o = 16; o; o >>= 1) {
        s  += __shfl_xor_sync(0xffffffffu, s, o);
        ss += __shfl_xor_sync(0xffffffffu, ss, o);
    }
    if ((t & 31) == 0) { red0[t >> 5] = s; red1[t >> 5] = ss; }
    __syncthreads();
    if (t < 32) {
        float a = (t < T / 32) ? red0[t] : 0.f;
        float c = (t < T / 32) ? red1[t] : 0.f;
#pragma unroll
        for (int o = 4; o; o >>= 1) {
            a += __shfl_xor_sync(0xffffffffu, a, o);
            c += __shfl_xor_sync(0xffffffffu, c, o);
        }
        if (t == 0) { red0[0] = a; red1[0] = c; }
    }
    __syncthreads();
    const float m = red0[0] * (1.f / N);
    const float var = red1[0] * (1.f / N) - m * m;
    const float r = rsqrtf(var + 1e-5f);
#pragma unroll
    for (int i = 0; i < PER; i++) {
        const int j = t + i * T;
        const float y = tanhf((yv[i] - m) * r * g[j] + be[j]);
        __nv_bfloat16 h, l;
        split2(y, h, l);
        outh[(long)row * N + j] = h;
        outl[(long)row * N + j] = l;
    }
}

// ---------------------------------------------------------------------------
// qs = (sin(amp*f0+p0) + cos(phase*f1+p1) + tanh(p2)) / 3, split-bf16 out
// ---------------------------------------------------------------------------
__global__ void qs_kernel(const float* __restrict__ amp,
                          const float* __restrict__ phase,
                          const float* __restrict__ rot_freq,
                          const float* __restrict__ rot_phase,
                          __nv_bfloat16* __restrict__ qsh,
                          __nv_bfloat16* __restrict__ qsl) {
    const int idx = blockIdx.x * blockDim.x + threadIdx.x;
    const int j = idx & (QDIM - 1);
    const int base = (4 * QDIM + j) * 3;
    const float f0 = rot_freq[base + 0];
    const float f1 = rot_freq[base + 1];
    const float p0 = rot_phase[base + 0];
    const float p1 = rot_phase[base + 1];
    const float p2 = rot_phase[base + 2];
    const float rx = sinf(fmaf(amp[idx],   f0, p0));
    const float ry = cosf(fmaf(phase[idx], f1, p1));
    const float rz = tanhf(p2);
    __nv_bfloat16 h, l;
    split2((rx + ry + rz) * (1.f / 3.f), h, l);
    qsh[idx] = h; qsl[idx] = l;
}

// ---------------------------------------------------------------------------
// Launch
// ---------------------------------------------------------------------------
extern "C" void kernel_launch(void* const* d_in, const int* in_sizes, int n_in,
                              void* d_out, int out_size) {
    const float* x        = (const float*)d_in[0];
    const float* amp_W1   = (const float*)d_in[1];
    const float* amp_b1   = (const float*)d_in[2];
    const float* amp_g1   = (const float*)d_in[3];
    const float* amp_be1  = (const float*)d_in[4];
    const float* amp_W2   = (const float*)d_in[5];
    const float* amp_b2   = (const float*)d_in[6];
    const float* amp_g2   = (const float*)d_in[7];
    const float* amp_be2  = (const float*)d_in[8];
    const float* amp_W3   = (const float*)d_in[9];
    const float* amp_b3   = (const float*)d_in[10];
    const float* ph_W1    = (const float*)d_in[11];
    const float* ph_b1    = (const float*)d_in[12];
    const float* ph_g1    = (const float*)d_in[13];
    const float* ph_be1   = (const float*)d_in[14];
    const float* ph_W2    = (const float*)d_in[15];
    const float* ph_b2    = (const float*)d_in[16];
    const float* rot_freq = (const float*)d_in[17];
    const float* rot_phase= (const float*)d_in[18];
    const float* attn_in_w= (const float*)d_in[19];
    const float* attn_in_b= (const float*)d_in[20];
    const float* attn_out_w=(const float*)d_in[21];
    const float* attn_out_b=(const float*)d_in[22];
    float* out = (float*)d_out;

    __nv_bfloat16 *h1h, *h1l, *ph, *pl, *h2h, *h2l, *qsh, *qsl, *vh, *vl;
    __nv_bfloat16 *w2h, *w2l, *w3h, *w3l, *pw2h, *pw2l, *wvh, *wvl, *woh, *wol;
    float *h2f, *ampf, *phasef;
    cudaGetSymbolAddress((void**)&h1h, g_h1h);  cudaGetSymbolAddress((void**)&h1l, g_h1l);
    cudaGetSymbolAddress((void**)&ph,  g_ph);   cudaGetSymbolAddress((void**)&pl,  g_pl);
    cudaGetSymbolAddress((void**)&h2f, g_h2f);
    cudaGetSymbolAddress((void**)&h2h, g_h2h);  cudaGetSymbolAddress((void**)&h2l, g_h2l);
    cudaGetSymbolAddress((void**)&ampf, g_ampf);
    cudaGetSymbolAddress((void**)&phasef, g_phasef);
    cudaGetSymbolAddress((void**)&qsh, g_qsh);  cudaGetSymbolAddress((void**)&qsl, g_qsl);
    cudaGetSymbolAddress((void**)&vh,  g_vh);   cudaGetSymbolAddress((void**)&vl,  g_vl);
    cudaGetSymbolAddress((void**)&w2h, g_w2h);  cudaGetSymbolAddress((void**)&w2l, g_w2l);
    cudaGetSymbolAddress((void**)&w3h, g_w3h);  cudaGetSymbolAddress((void**)&w3l, g_w3l);
    cudaGetSymbolAddress((void**)&pw2h, g_pw2h); cudaGetSymbolAddress((void**)&pw2l, g_pw2l);
    cudaGetSymbolAddress((void**)&wvh, g_wvh);  cudaGetSymbolAddress((void**)&wvl, g_wvl);
    cudaGetSymbolAddress((void**)&woh, g_woh);  cudaGetSymbolAddress((void**)&wol, g_wol);

    static bool attr_done = false;
    if (!attr_done) {
        cudaFuncSetAttribute(tc_gemm<0>, cudaFuncAttributeMaxDynamicSharedMemorySize, 2 * STAGE_BYTES);
        cudaFuncSetAttribute(tc_gemm<1>, cudaFuncAttributeMaxDynamicSharedMemorySize, 2 * STAGE_BYTES);
        cudaFuncSetAttribute(tc_gemm<2>, cudaFuncAttributeMaxDynamicSharedMemorySize, 2 * STAGE_BYTES);
        attr_done = true;
    }
    const size_t dsm = 2 * STAGE_BYTES;

    // Weight splits
    {
        int n;
        n = 2 * QDIM * 4 * QDIM; split_kernel<<<(n + 255) / 256, 256>>>(amp_W2, w2h, w2l, n);
        n = QDIM * 2 * QDIM;     split_kernel<<<(n + 255) / 256, 256>>>(amp_W3, w3h, w3l, n);
        n = QDIM * 2 * QDIM;     split_kernel<<<(n + 255) / 256, 256>>>(ph_W2,  pw2h, pw2l, n);
        n = QDIM * QDIM;         split_kernel<<<(n + 255) / 256, 256>>>(attn_in_w + (long)2 * QDIM * QDIM, wvh, wvl, n);
        n = QDIM * QDIM;         split_kernel<<<(n + 255) / 256, 256>>>(attn_out_w, woh, wol, n);
    }

    // amp layer 1: x -> h1 split (B x 4096), LN + gelu
    first_layer_kernel<4 * QDIM, 0><<<BROWS, 256>>>(x, amp_W1, amp_b1, amp_g1, amp_be1, h1h, h1l);
    // ph layer 1: x -> p split (B x 2048), LN + silu
    first_layer_kernel<2 * QDIM, 1><<<BROWS, 256>>>(x, ph_W1, ph_b1, ph_g1, ph_be1, ph, pl);

    // h2pre = h1 @ W2^T + b2  (16384 x 2048, K=4096), fp32 out
    {
        dim3 grid(2 * QDIM / TCG_BN, BROWS / TCG_BM);
        tc_gemm<0><<<grid, 256, dsm>>>(h1h, h1l, w2h, w2l, amp_b2, h2f, nullptr, nullptr, 2 * QDIM, 4 * QDIM);
    }
    // h2 = tanh(LN(h2pre)), split out
    ln_tanh_split_kernel<2 * QDIM><<<BROWS, 256>>>(h2f, amp_g2, amp_be2, h2h, h2l);

    // amp = h2 @ W3^T + b3  (16384 x 1024, K=2048), fp32 out
    {
        dim3 grid(QDIM / TCG_BN, BROWS / TCG_BM);
        tc_gemm<0><<<grid, 256, dsm>>>(h2h, h2l, w3h, w3l, amp_b3, ampf, nullptr, nullptr, QDIM, 2 * QDIM);
    }
    // phase = tanh(p @ ph_W2^T + b2)  (16384 x 1024, K=2048)
    {
        dim3 grid(QDIM / TCG_BN, BROWS / TCG_BM);
        tc_gemm<1><<<grid, 256, dsm>>>(ph, pl, pw2h, pw2l, ph_b2, phasef, nullptr, nullptr, QDIM, 2 * QDIM);
    }

    // qs elementwise, split out
    qs_kernel<<<(BROWS * QDIM) / 256, 256>>>(ampf, phasef, rot_freq, rot_phase, qsh, qsl);

    // v = qs @ Wv^T + bv  (K=1024), split out
    {
        dim3 grid(QDIM / TCG_BN, BROWS / TCG_BM);
        tc_gemm<2><<<grid, 256, dsm>>>(qsh, qsl, wvh, wvl, attn_in_b + 2 * QDIM, nullptr, vh, vl, QDIM, QDIM);
    }
    // out = v @ Wo^T + bo  (K=1024), fp32 out
    {
        dim3 grid(QDIM / TCG_BN, BROWS / TCG_BM);
        tc_gemm<0><<<grid, 256, dsm>>>(vh, vl, woh, wol, attn_out_b, out, nullptr, nullptr, QDIM, QDIM);
    }
}

// round 12
// speedup vs baseline: 2.9116x; 1.0335x over previous
#include <cuda_runtime.h>
#include <cuda_bf16.h>
#include <math.h>
#include <stdint.h>

// Problem constants
#define BROWS 16384
#define QDIM  1024

// ---------------------------------------------------------------------------
// Scratch (static device globals)
// ---------------------------------------------------------------------------
__device__ __align__(16) __nv_bfloat16 g_h1h[BROWS * 4 * QDIM];
__device__ __align__(16) __nv_bfloat16 g_h1l[BROWS * 4 * QDIM];
__device__ __align__(16) __nv_bfloat16 g_ph [BROWS * 2 * QDIM];
__device__ __align__(16) __nv_bfloat16 g_pl [BROWS * 2 * QDIM];
__device__ __align__(16) float         g_h2f[BROWS * 2 * QDIM];
__device__ __align__(16) __nv_bfloat16 g_h2h[BROWS * 2 * QDIM];
__device__ __align__(16) __nv_bfloat16 g_h2l[BROWS * 2 * QDIM];
__device__ __align__(16) float         g_ampf  [BROWS * QDIM];
__device__ __align__(16) float         g_phasef[BROWS * QDIM];
__device__ __align__(16) __nv_bfloat16 g_qsh[BROWS * QDIM];
__device__ __align__(16) __nv_bfloat16 g_qsl[BROWS * QDIM];
__device__ __align__(16) __nv_bfloat16 g_vh [BROWS * QDIM];
__device__ __align__(16) __nv_bfloat16 g_vl [BROWS * QDIM];
// weights (hi/lo)
__device__ __align__(16) __nv_bfloat16 g_w2h [2 * QDIM * 4 * QDIM];
__device__ __align__(16) __nv_bfloat16 g_w2l [2 * QDIM * 4 * QDIM];
__device__ __align__(16) __nv_bfloat16 g_w3h [QDIM * 2 * QDIM];
__device__ __align__(16) __nv_bfloat16 g_w3l [QDIM * 2 * QDIM];
__device__ __align__(16) __nv_bfloat16 g_pw2h[QDIM * 2 * QDIM];
__device__ __align__(16) __nv_bfloat16 g_pw2l[QDIM * 2 * QDIM];
__device__ __align__(16) __nv_bfloat16 g_wvh [QDIM * QDIM];
__device__ __align__(16) __nv_bfloat16 g_wvl [QDIM * QDIM];
__device__ __align__(16) __nv_bfloat16 g_woh [QDIM * QDIM];
__device__ __align__(16) __nv_bfloat16 g_wol [QDIM * QDIM];

// ---------------------------------------------------------------------------
// sm_80-level PTX helpers only (cp.async, ldmatrix, mma.sync)
// ---------------------------------------------------------------------------
__device__ __forceinline__ uint32_t smem_u32(const void* p) {
    uint32_t a;
    asm("{ .reg .u64 t; cvta.to.shared.u64 t, %1; cvt.u32.u64 %0, t; }" : "=r"(a) : "l"(p));
    return a;
}
__device__ __forceinline__ void cp16(uint32_t s, const void* g) {
    asm volatile("cp.async.cg.shared.global [%0], [%1], 16;\n" :: "r"(s), "l"(g));
}
__device__ __forceinline__ void cp_commit() {
    asm volatile("cp.async.commit_group;\n" ::: "memory");
}
__device__ __forceinline__ void cp_wait1() {
    asm volatile("cp.async.wait_group 1;\n" ::: "memory");
}
__device__ __forceinline__ void cp_wait0() {
    asm volatile("cp.async.wait_group 0;\n" ::: "memory");
}
__device__ __forceinline__ void ldsm_x4(uint32_t* r, uint32_t addr) {
    asm volatile("ldmatrix.sync.aligned.m8n8.x4.shared.b16 {%0,%1,%2,%3}, [%4];"
        : "=r"(r[0]), "=r"(r[1]), "=r"(r[2]), "=r"(r[3]) : "r"(addr));
}
__device__ __forceinline__ void ldsm_x2(uint32_t* r, uint32_t addr) {
    asm volatile("ldmatrix.sync.aligned.m8n8.x2.shared.b16 {%0,%1}, [%2];"
        : "=r"(r[0]), "=r"(r[1]) : "r"(addr));
}
__device__ __forceinline__ void mma_bf16(float* c, const uint32_t* a, const uint32_t* b) {
    asm volatile(
        "mma.sync.aligned.m16n8k16.row.col.f32.bf16.bf16.f32 "
        "{%0,%1,%2,%3}, {%4,%5,%6,%7}, {%8,%9}, {%0,%1,%2,%3};"
        : "+f"(c[0]), "+f"(c[1]), "+f"(c[2]), "+f"(c[3])
        : "r"(a[0]), "r"(a[1]), "r"(a[2]), "r"(a[3]), "r"(b[0]), "r"(b[1]));
}
__device__ __forceinline__ void split2(float x, __nv_bfloat16& h, __nv_bfloat16& l) {
    h = __float2bfloat16(x);
    l = __float2bfloat16(x - __bfloat162float(h));
}

// ---------------------------------------------------------------------------
// Tensor-core GEMM via mma.sync (HMMA): C[m][n] = sum_k A[m][k]*B[n][k] + bias[n]
// A,B fp32 split into (hi,lo) bf16 K-major buffers; 3-way split accumulation.
// BM=128, BN=128, BK=64, 256 threads, warp tile 64x32.
// 3-stage cp.async pipeline, race-free ordering:
//   prologue loads chunks 0,1; per iter: wait -> barrier -> issue c+2 -> compute c
// Split-term loop is OUTERMOST within each k-step so consecutive HMMAs never
// share an accumulator.
// EPI: 0 = fp32 out (+bias), 1 = bias+tanh fp32 out, 2 = split bf16 out
// ---------------------------------------------------------------------------
#define TCG_BM 128
#define TCG_BN 128
#define TCG_BK 64
// SMEM tile: 128 rows x 64 bf16 (128B), padded to 144B/row (conflict-free ldsm)
#define ROWB 144u
#define TILE_BYTES (128u * ROWB)        // 18432
#define OFF_AH 0u
#define OFF_AL (TILE_BYTES)
#define OFF_BH (2u * TILE_BYTES)
#define OFF_BL (3u * TILE_BYTES)
#define STAGE_BYTES (4u * TILE_BYTES)   // 73728
#define NSTAGE 3
#define SMEM_TOTAL (NSTAGE * STAGE_BYTES) // 221184 <= 227KB carveout

template<int EPI>
__global__ __launch_bounds__(256)
void tc_gemm(const __nv_bfloat16* __restrict__ Ah, const __nv_bfloat16* __restrict__ Al,
             const __nv_bfloat16* __restrict__ Bh, const __nv_bfloat16* __restrict__ Bl,
             const float* __restrict__ bias,
             float* __restrict__ Cf,
             __nv_bfloat16* __restrict__ Chi, __nv_bfloat16* __restrict__ Clo,
             int N, int K) {
    extern __shared__ char dynsmem[];
    const uint32_t sbase = smem_u32(dynsmem);
    const int t = threadIdx.x;
    const int wid = t >> 5;
    const int lane = t & 31;
    const int wm = wid & 1;        // 2 warps over M (64 each)
    const int wn = wid >> 1;       // 4 warps over N (32 each)
    const int bm = blockIdx.y * TCG_BM;
    const int bn = blockIdx.x * TCG_BN;

    float acc[4][4][4];
#pragma unroll
    for (int i = 0; i < 4; i++)
#pragma unroll
        for (int j = 0; j < 4; j++)
#pragma unroll
            for (int q = 0; q < 4; q++) acc[i][j][q] = 0.f;

    const int C = K / TCG_BK;

    // Tile row = 64 bf16 = 128 bytes = 8 x 16B chunks.
    // 128 rows x 8 chunks = 1024 chunks per tile; 256 threads x 4 iters.
    auto load_chunk = [&](int c, int stg) {
        const int k0 = c * TCG_BK;
        const uint32_t base = sbase + (uint32_t)stg * STAGE_BYTES;
#pragma unroll
        for (int i = 0; i < 4; i++) {
            const int idx = t + i * 256;          // 0..1023
            const int row = idx >> 3, cc = idx & 7;
            const uint32_t so = (uint32_t)row * ROWB + cc * 16;
            const size_t gA = (size_t)(bm + row) * K + k0 + cc * 8;
            const size_t gB = (size_t)(bn + row) * K + k0 + cc * 8;
            cp16(base + OFF_AH + so, Ah + gA);
            cp16(base + OFF_AL + so, Al + gA);
            cp16(base + OFF_BH + so, Bh + gB);
            cp16(base + OFF_BL + so, Bl + gB);
        }
        cp_commit();
    };

    // ldmatrix lane->address components (constant over loop)
    const int a_row = wm * 64 + (lane & 15);
    const int a_colh = (lane >> 4) * 8;           // 0 or 8 (k halves)
    const int b_row = wn * 32 + (lane & 7);
    const int b_colh = ((lane >> 3) & 1) * 8;

    // prologue: stages 0,1
    load_chunk(0, 0);
    load_chunk(1, 1);

    int cs = 0;           // compute stage for chunk c
    int ls = 2;           // load stage for chunk c+2
    for (int c = 0; c < C; ++c) {
        // ensure chunk c (this thread's group) has landed
        if (c == C - 1) cp_wait0(); else cp_wait1();
        // collective: now ALL threads' loads of stage cs are complete;
        // also bounds warp drift so issuing into stage ls below is safe
        __syncthreads();
        if (c + 2 < C) load_chunk(c + 2, ls);

        const uint32_t base = sbase + (uint32_t)cs * STAGE_BYTES;
#pragma unroll
        for (int ks = 0; ks < 4; ks++) {
            const int kof = ks * 16;
            uint32_t ah[4][4], al[4][4], bh[4][2], bl[4][2];
#pragma unroll
            for (int fm = 0; fm < 4; fm++) {
                const uint32_t off = (uint32_t)(a_row + fm * 16) * ROWB + (kof + a_colh) * 2;
                ldsm_x4(ah[fm], base + OFF_AH + off);
                ldsm_x4(al[fm], base + OFF_AL + off);
            }
#pragma unroll
            for (int fn = 0; fn < 4; fn++) {
                const uint32_t off = (uint32_t)(b_row + fn * 8) * ROWB + (kof + b_colh) * 2;
                ldsm_x2(bh[fn], base + OFF_BH + off);
                ldsm_x2(bl[fn], base + OFF_BL + off);
            }
            // split term OUTERMOST: same acc is 16 mmas apart, no RAW stalls
#pragma unroll
            for (int fm = 0; fm < 4; fm++)
#pragma unroll
                for (int fn = 0; fn < 4; fn++)
                    mma_bf16(acc[fm][fn], ah[fm], bh[fn]);
#pragma unroll
            for (int fm = 0; fm < 4; fm++)
#pragma unroll
                for (int fn = 0; fn < 4; fn++)
                    mma_bf16(acc[fm][fn], ah[fm], bl[fn]);
#pragma unroll
            for (int fm = 0; fm < 4; fm++)
#pragma unroll
                for (int fn = 0; fn < 4; fn++)
                    mma_bf16(acc[fm][fn], al[fm], bh[fn]);
        }
        // advance ring
        cs = (cs == NSTAGE - 1) ? 0 : cs + 1;
        ls = (ls == NSTAGE - 1) ? 0 : ls + 1;
    }

    // ---- epilogue ----
    const int row0 = bm + wm * 64 + (lane >> 2);
    const int colb = bn + wn * 32 + (lane & 3) * 2;
#pragma unroll
    for (int fm = 0; fm < 4; fm++) {
        const long r0 = row0 + fm * 16;
        const long r1 = r0 + 8;
#pragma unroll
        for (int fn = 0; fn < 4; fn++) {
            const int col = colb + fn * 8;
            const float b0 = bias[col], b1 = bias[col + 1];
            float y00 = acc[fm][fn][0] + b0;
            float y01 = acc[fm][fn][1] + b1;
            float y10 = acc[fm][fn][2] + b0;
            float y11 = acc[fm][fn][3] + b1;
            if (EPI == 1) {
                y00 = tanhf(y00); y01 = tanhf(y01);
                y10 = tanhf(y10); y11 = tanhf(y11);
            }
            if (EPI == 0 || EPI == 1) {
                *(float2*)(Cf + r0 * N + col) = make_float2(y00, y01);
                *(float2*)(Cf + r1 * N + col) = make_float2(y10, y11);
            } else {
                __nv_bfloat16 h0, l0, h1, l1;
                __nv_bfloat162 hv, lv;
                split2(y00, h0, l0); split2(y01, h1, l1);
                hv.x = h0; hv.y = h1; lv.x = l0; lv.y = l1;
                *(__nv_bfloat162*)(Chi + r0 * N + col) = hv;
                *(__nv_bfloat162*)(Clo + r0 * N + col) = lv;
                split2(y10, h0, l0); split2(y11, h1, l1);
                hv.x = h0; hv.y = h1; lv.x = l0; lv.y = l1;
                *(__nv_bfloat162*)(Chi + r1 * N + col) = hv;
                *(__nv_bfloat162*)(Clo + r1 * N + col) = lv;
            }
        }
    }
}

// ---------------------------------------------------------------------------
// Weight split: fp32 -> (hi, lo) bf16
// ---------------------------------------------------------------------------
__global__ void split_kernel(const float* __restrict__ src,
                             __nv_bfloat16* __restrict__ hi,
                             __nv_bfloat16* __restrict__ lo, int n) {
    const int i = blockIdx.x * 256 + threadIdx.x;
    if (i < n) {
        __nv_bfloat16 h, l;
        split2(src[i], h, l);
        hi[i] = h; lo[i] = l;
    }
}

// ---------------------------------------------------------------------------
// First layer: y = x @ W^T + b (K=2), LN, activation, split-bf16 out.
// ACT: 0 = exact gelu, 1 = silu
// ---------------------------------------------------------------------------
template<int N, int ACT>
__global__ __launch_bounds__(256)
void first_layer_kernel(const float* __restrict__ x,
                        const float* __restrict__ W,
                        const float* __restrict__ b,
                        const float* __restrict__ g,
                        const float* __restrict__ be,
                        __nv_bfloat16* __restrict__ outh,
                        __nv_bfloat16* __restrict__ outl) {
    constexpr int T = 256;
    constexpr int PER = N / T;
    const int row = blockIdx.x;
    const int t = threadIdx.x;
    const float x0 = x[row * 2 + 0];
    const float x1 = x[row * 2 + 1];

    float yv[PER];
    float s = 0.f, ss = 0.f;
#pragma unroll
    for (int i = 0; i < PER; i++) {
        const int j = t + i * T;
        const float y = fmaf(x0, W[2 * j], fmaf(x1, W[2 * j + 1], b[j]));
        yv[i] = y; s += y; ss += y * y;
    }
    __shared__ float red0[T / 32];
    __shared__ float red1[T / 32];
#pragma unroll
    for (int o = 16; o; o >>= 1) {
        s  += __shfl_xor_sync(0xffffffffu, s, o);
        ss += __shfl_xor_sync(0xffffffffu, ss, o);
    }
    if ((t & 31) == 0) { red0[t >> 5] = s; red1[t >> 5] = ss; }
    __syncthreads();
    if (t < 32) {
        float a = (t < T / 32) ? red0[t] : 0.f;
        float c = (t < T / 32) ? red1[t] : 0.f;
#pragma unroll
        for (int o = 4; o; o >>= 1) {
            a += __shfl_xor_sync(0xffffffffu, a, o);
            c += __shfl_xor_sync(0xffffffffu, c, o);
        }
        if (t == 0) { red0[0] = a; red1[0] = c; }
    }
    __syncthreads();
    const float m = red0[0] * (1.f / N);
    const float var = red1[0] * (1.f / N) - m * m;
    const float r = rsqrtf(var + 1e-5f);
#pragma unroll
    for (int i = 0; i < PER; i++) {
        const int j = t + i * T;
        const float v = (yv[i] - m) * r * g[j] + be[j];
        float o;
        if (ACT == 0) o = 0.5f * v * (1.f + erff(v * 0.70710678118654752f));
        else          o = v / (1.f + expf(-v));
        __nv_bfloat16 h, l;
        split2(o, h, l);
        outh[(long)row * N + j] = h;
        outl[(long)row * N + j] = l;
    }
}

// ---------------------------------------------------------------------------
// LN + tanh: fp32 in, split bf16 out
// ---------------------------------------------------------------------------
template<int N>
__global__ __launch_bounds__(256)
void ln_tanh_split_kernel(const float* __restrict__ in,
                          const float* __restrict__ g,
                          const float* __restrict__ be,
                          __nv_bfloat16* __restrict__ outh,
                          __nv_bfloat16* __restrict__ outl) {
    constexpr int T = 256;
    constexpr int PER = N / T;
    const int row = blockIdx.x;
    const int t = threadIdx.x;
    float yv[PER];
    float s = 0.f, ss = 0.f;
#pragma unroll
    for (int i = 0; i < PER; i++) {
        const float y = in[(long)row * N + t + i * T];
        yv[i] = y; s += y; ss += y * y;
    }
    __shared__ float red0[T / 32];
    __shared__ float red1[T / 32];
#pragma unroll
    for (int o = 16; o; o >>= 1) {
        s  += __shfl_xor_sync(0xffffffffu, s, o);
        ss += __shfl_xor_sync(0xffffffffu, ss, o);
    }
    if ((t & 31) == 0) { red0[t >> 5] = s; red1[t >> 5] = ss; }
    __syncthreads();
    if (t < 32) {
        float a = (t < T / 32) ? red0[t] : 0.f;
        float c = (t < T / 32) ? red1[t] : 0.f;
#pragma unroll
        for (int o = 4; o; o >>= 1) {
            a += __shfl_xor_sync(0xffffffffu, a, o);
            c += __shfl_xor_sync(0xffffffffu, c, o);
        }
        if (t == 0) { red0[0] = a; red1[0] = c; }
    }
    __syncthreads();
    const float m = red0[0] * (1.f / N);
    const float var = red1[0] * (1.f / N) - m * m;
    const float r = rsqrtf(var + 1e-5f);
#pragma unroll
    for (int i = 0; i < PER; i++) {
        const int j = t + i * T;
        const float y = tanhf((yv[i] - m) * r * g[j] + be[j]);
        __nv_bfloat16 h, l;
        split2(y, h, l);
        outh[(long)row * N + j] = h;
        outl[(long)row * N + j] = l;
    }
}

// ---------------------------------------------------------------------------
// qs = (sin(amp*f0+p0) + cos(phase*f1+p1) + tanh(p2)) / 3, split-bf16 out
// ---------------------------------------------------------------------------
__global__ void qs_kernel(const float* __restrict__ amp,
                          const float* __restrict__ phase,
                          const float* __restrict__ rot_freq,
                          const float* __restrict__ rot_phase,
                          __nv_bfloat16* __restrict__ qsh,
                          __nv_bfloat16* __restrict__ qsl) {
    const int idx = blockIdx.x * blockDim.x + threadIdx.x;
    const int j = idx & (QDIM - 1);
    const int base = (4 * QDIM + j) * 3;
    const float f0 = rot_freq[base + 0];
    const float f1 = rot_freq[base + 1];
    const float p0 = rot_phase[base + 0];
    const float p1 = rot_phase[base + 1];
    const float p2 = rot_phase[base + 2];
    const float rx = sinf(fmaf(amp[idx],   f0, p0));
    const float ry = cosf(fmaf(phase[idx], f1, p1));
    const float rz = tanhf(p2);
    __nv_bfloat16 h, l;
    split2((rx + ry + rz) * (1.f / 3.f), h, l);
    qsh[idx] = h; qsl[idx] = l;
}

// ---------------------------------------------------------------------------
// Launch
// ---------------------------------------------------------------------------
extern "C" void kernel_launch(void* const* d_in, const int* in_sizes, int n_in,
                              void* d_out, int out_size) {
    const float* x        = (const float*)d_in[0];
    const float* amp_W1   = (const float*)d_in[1];
    const float* amp_b1   = (const float*)d_in[2];
    const float* amp_g1   = (const float*)d_in[3];
    const float* amp_be1  = (const float*)d_in[4];
    const float* amp_W2   = (const float*)d_in[5];
    const float* amp_b2   = (const float*)d_in[6];
    const float* amp_g2   = (const float*)d_in[7];
    const float* amp_be2  = (const float*)d_in[8];
    const float* amp_W3   = (const float*)d_in[9];
    const float* amp_b3   = (const float*)d_in[10];
    const float* ph_W1    = (const float*)d_in[11];
    const float* ph_b1    = (const float*)d_in[12];
    const float* ph_g1    = (const float*)d_in[13];
    const float* ph_be1   = (const float*)d_in[14];
    const float* ph_W2    = (const float*)d_in[15];
    const float* ph_b2    = (const float*)d_in[16];
    const float* rot_freq = (const float*)d_in[17];
    const float* rot_phase= (const float*)d_in[18];
    const float* attn_in_w= (const float*)d_in[19];
    const float* attn_in_b= (const float*)d_in[20];
    const float* attn_out_w=(const float*)d_in[21];
    const float* attn_out_b=(const float*)d_in[22];
    float* out = (float*)d_out;

    __nv_bfloat16 *h1h, *h1l, *ph, *pl, *h2h, *h2l, *qsh, *qsl, *vh, *vl;
    __nv_bfloat16 *w2h, *w2l, *w3h, *w3l, *pw2h, *pw2l, *wvh, *wvl, *woh, *wol;
    float *h2f, *ampf, *phasef;
    cudaGetSymbolAddress((void**)&h1h, g_h1h);  cudaGetSymbolAddress((void**)&h1l, g_h1l);
    cudaGetSymbolAddress((void**)&ph,  g_ph);   cudaGetSymbolAddress((void**)&pl,  g_pl);
    cudaGetSymbolAddress((void**)&h2f, g_h2f);
    cudaGetSymbolAddress((void**)&h2h, g_h2h);  cudaGetSymbolAddress((void**)&h2l, g_h2l);
    cudaGetSymbolAddress((void**)&ampf, g_ampf);
    cudaGetSymbolAddress((void**)&phasef, g_phasef);
    cudaGetSymbolAddress((void**)&qsh, g_qsh);  cudaGetSymbolAddress((void**)&qsl, g_qsl);
    cudaGetSymbolAddress((void**)&vh,  g_vh);   cudaGetSymbolAddress((void**)&vl,  g_vl);
    cudaGetSymbolAddress((void**)&w2h, g_w2h);  cudaGetSymbolAddress((void**)&w2l, g_w2l);
    cudaGetSymbolAddress((void**)&w3h, g_w3h);  cudaGetSymbolAddress((void**)&w3l, g_w3l);
    cudaGetSymbolAddress((void**)&pw2h, g_pw2h); cudaGetSymbolAddress((void**)&pw2l, g_pw2l);
    cudaGetSymbolAddress((void**)&wvh, g_wvh);  cudaGetSymbolAddress((void**)&wvl, g_wvl);
    cudaGetSymbolAddress((void**)&woh, g_woh);  cudaGetSymbolAddress((void**)&wol, g_wol);

    static bool attr_done = false;
    if (!attr_done) {
        cudaFuncSetAttribute(tc_gemm<0>, cudaFuncAttributeMaxDynamicSharedMemorySize, SMEM_TOTAL);
        cudaFuncSetAttribute(tc_gemm<1>, cudaFuncAttributeMaxDynamicSharedMemorySize, SMEM_TOTAL);
        cudaFuncSetAttribute(tc_gemm<2>, cudaFuncAttributeMaxDynamicSharedMemorySize, SMEM_TOTAL);
        attr_done = true;
    }
    const size_t dsm = SMEM_TOTAL;

    // Weight splits
    {
        int n;
        n = 2 * QDIM * 4 * QDIM; split_kernel<<<(n + 255) / 256, 256>>>(amp_W2, w2h, w2l, n);
        n = QDIM * 2 * QDIM;     split_kernel<<<(n + 255) / 256, 256>>>(amp_W3, w3h, w3l, n);
        n = QDIM * 2 * QDIM;     split_kernel<<<(n + 255) / 256, 256>>>(ph_W2,  pw2h, pw2l, n);
        n = QDIM * QDIM;         split_kernel<<<(n + 255) / 256, 256>>>(attn_in_w + (long)2 * QDIM * QDIM, wvh, wvl, n);
        n = QDIM * QDIM;         split_kernel<<<(n + 255) / 256, 256>>>(attn_out_w, woh, wol, n);
    }

    // amp layer 1: x -> h1 split (B x 4096), LN + gelu
    first_layer_kernel<4 * QDIM, 0><<<BROWS, 256>>>(x, amp_W1, amp_b1, amp_g1, amp_be1, h1h, h1l);
    // ph layer 1: x -> p split (B x 2048), LN + silu
    first_layer_kernel<2 * QDIM, 1><<<BROWS, 256>>>(x, ph_W1, ph_b1, ph_g1, ph_be1, ph, pl);

    // h2pre = h1 @ W2^T + b2  (16384 x 2048, K=4096), fp32 out
    {
        dim3 grid(2 * QDIM / TCG_BN, BROWS / TCG_BM);
        tc_gemm<0><<<grid, 256, dsm>>>(h1h, h1l, w2h, w2l, amp_b2, h2f, nullptr, nullptr, 2 * QDIM, 4 * QDIM);
    }
    // h2 = tanh(LN(h2pre)), split out
    ln_tanh_split_kernel<2 * QDIM><<<BROWS, 256>>>(h2f, amp_g2, amp_be2, h2h, h2l);

    // amp = h2 @ W3^T + b3  (16384 x 1024, K=2048), fp32 out
    {
        dim3 grid(QDIM / TCG_BN, BROWS / TCG_BM);
        tc_gemm<0><<<grid, 256, dsm>>>(h2h, h2l, w3h, w3l, amp_b3, ampf, nullptr, nullptr, QDIM, 2 * QDIM);
    }
    // phase = tanh(p @ ph_W2^T + b2)  (16384 x 1024, K=2048)
    {
        dim3 grid(QDIM / TCG_BN, BROWS / TCG_BM);
        tc_gemm<1><<<grid, 256, dsm>>>(ph, pl, pw2h, pw2l, ph_b2, phasef, nullptr, nullptr, QDIM, 2 * QDIM);
    }

    // qs elementwise, split out
    qs_kernel<<<(BROWS * QDIM) / 256, 256>>>(ampf, phasef, rot_freq, rot_phase, qsh, qsl);

    // v = qs @ Wv^T + bv  (K=1024), split out
    {
        dim3 grid(QDIM / TCG_BN, BROWS / TCG_BM);
        tc_gemm<2><<<grid, 256, dsm>>>(qsh, qsl, wvh, wvl, attn_in_b + 2 * QDIM, nullptr, vh, vl, QDIM, QDIM);
    }
    // out = v @ Wo^T + bo  (K=1024), fp32 out
    {
        dim3 grid(QDIM / TCG_BN, BROWS / TCG_BM);
        tc_gemm<0><<<grid, 256, dsm>>>(vh, vl, woh, wol, attn_out_b, out, nullptr, nullptr, QDIM, QDIM);
    }
}